// round 1
// baseline (speedup 1.0000x reference)
#include <cuda_runtime.h>

#define BB 16
#define CC 64
#define HH 192
#define WW 192
#define HT 64   // pooled spatial size

// scratch (static device globals -- no runtime allocation allowed)
__device__ float g_xtem[BB*CC*HT*HT];
__device__ float g_gate[BB*CC*HT*HT];

// -------------------------------------------------------------------------
// Kernel 1: fused maxpool3x3(stride1,pad1) + blurpool(4x4, stride3, reflect(1,2))
// One block = 4 output rows x 64 cols of one (b,c) plane.
// -------------------------------------------------------------------------
__global__ void k_pool(const float* __restrict__ x) {
    __shared__ float sx[15][193];   // raw input rows (padded stride vs bank conflicts)
    __shared__ float hm[15][193];   // horizontal 3-max
    int plane = blockIdx.y;
    int ohg   = blockIdx.x;               // group of 4 output rows
    int r0    = 3*(ohg*4) - 2;            // first input row needed (may be -2)
    const float* xp = x + (size_t)plane * (HH*WW);
    int tid = threadIdx.y*64 + threadIdx.x;

    for (int l = tid; l < 15*192; l += 256) {
        int sr = l / 192, cc = l % 192;
        int r = r0 + sr;
        sx[sr][cc] = (r >= 0 && r < HH) ? xp[r*WW + cc] : 0.f;
    }
    __syncthreads();
    for (int l = tid; l < 15*192; l += 256) {
        int sr = l / 192, cc = l % 192;
        float v = sx[sr][cc];
        if (cc > 0)   v = fmaxf(v, sx[sr][cc-1]);
        if (cc < 191) v = fmaxf(v, sx[sr][cc+1]);
        hm[sr][cc] = v;
    }
    __syncthreads();

    int ow = threadIdx.x;
    int oh = ohg*4 + threadIdx.y;
    const float W4[4] = {1.f, 3.f, 3.f, 1.f};
    float acc = 0.f;
    #pragma unroll
    for (int u = 0; u < 4; u++) {
        int pr = 3*oh - 1 + u;
        int mr = (pr < 0) ? 1 : pr;                 // reflect (only -1 occurs)
        int ra = max(mr-1, 0)   - r0;
        int rb = mr             - r0;
        int rc = min(mr+1, 191) - r0;
        #pragma unroll
        for (int v = 0; v < 4; v++) {
            int pc = 3*ow - 1 + v;
            int mc = (pc < 0) ? 1 : pc;             // reflect
            float m = fmaxf(fmaxf(hm[ra][mc], hm[rb][mc]), hm[rc][mc]);
            acc += W4[u] * W4[v] * m;
        }
    }
    g_xtem[(size_t)plane*(HT*HT) + oh*HT + ow] = acc * (1.f/64.f);
}

// -------------------------------------------------------------------------
// Kernel 2: combined 4x depthwise-conv (87-tap sparse 13x13 stencil) + BN +
// sigmoid. One block per (b,c) plane; per-channel stencil built in smem.
// Thread layout: warp = 32 consecutive cols, each thread 16 rows (conflict-free).
// -------------------------------------------------------------------------
__global__ void k_att(const float* __restrict__ wh1, const float* __restrict__ wv1,
                      const float* __restrict__ wh2, const float* __restrict__ wv2,
                      const float* __restrict__ gamma, const float* __restrict__ beta,
                      const float* __restrict__ mean,  const float* __restrict__ var) {
    __shared__ float tile[76*80];   // 64x64 plane, halo 6, row stride 80, col off 8
    __shared__ float wc[169];       // combined 13x13 stencil for this channel
    int plane = blockIdx.x;
    int ch    = plane % CC;
    int tid   = threadIdx.x;

    float4 z4 = make_float4(0.f,0.f,0.f,0.f);
    for (int i = tid; i < (76*80)/4; i += 256) ((float4*)tile)[i] = z4;
    if (tid < 169) wc[tid] = 0.f;
    __syncthreads();
    // scatter the 4 conv kernels into one stencil (disjoint within each phase)
    if (tid < 33) { int a = tid/3  - 5, b = tid%3  - 1; wc[(a+6)*13 + (b+6)]     += wh1[ch*33 + tid]; }
    __syncthreads();
    if (tid < 33) { int a = tid/11 - 1, b = tid%11 - 5; wc[(a+6)*13 + (b+6)]     += wv1[ch*33 + tid]; }
    __syncthreads();
    if (tid < 33) { int a = tid/3  - 5, b = tid%3  - 1; wc[(a+6)*13 + (b-a+6)]   += wh2[ch*33 + tid]; }
    __syncthreads();
    if (tid < 33) { int s = tid/11 - 1, t = tid%11 - 5; wc[(s-t+6)*13 + (t+6)]   += wv2[ch*33 + tid]; }

    const float4* src = (const float4*)(g_xtem + (size_t)plane*(HT*HT));
    for (int i = tid; i < 1024; i += 256) {
        int r = i / 16, c4 = i % 16;
        *((float4*)&tile[(r+6)*80 + c4*4 + 8]) = src[i];
    }
    __syncthreads();

    int lane = tid & 31, w = tid >> 5;
    int c  = (w & 1)*32 + lane;     // output column (lane-consecutive)
    int r0 = (w >> 1)*16;           // first of 16 output rows
    float acc[16];
    #pragma unroll
    for (int k = 0; k < 16; k++) acc[k] = 0.f;

    // per-dj valid di ranges of the 87-tap pattern (index = dj+6)
    constexpr int LO[13] = {5,-1,-1,-1,-1,-5,-5,-5,-3,-4,-5,-6,-5};
    constexpr int HI[13] = {5, 6, 5, 4, 3, 5, 5, 5, 1, 1, 1, 1,-5};
    #pragma unroll
    for (int d = 0; d < 13; d++) {           // dj = d - 6
        int cidx = c + d + 2;                // tile col of (c + dj)
        float xr[28];                        // register column window
        #pragma unroll
        for (int m = LO[d]+6; m <= HI[d]+21; m++)
            xr[m] = tile[(r0 + m)*80 + cidx];
        #pragma unroll
        for (int di = LO[d]; di <= HI[d]; di++) {
            float wv = wc[(di+6)*13 + d];
            #pragma unroll
            for (int k = 0; k < 16; k++)
                acc[k] += wv * xr[k + di + 6];
        }
    }

    float inv = gamma[ch] * rsqrtf(var[ch] + 1e-5f);
    float b2  = beta[ch] - mean[ch]*inv;
    float* gp = g_gate + (size_t)plane*(HT*HT);
    #pragma unroll
    for (int k = 0; k < 16; k++) {
        float a = acc[k]*inv + b2;
        gp[(r0 + k)*HT + c] = 1.f / (1.f + __expf(-a));
    }
}

// -------------------------------------------------------------------------
// Kernel 3: out = x * gate[i/3, j/3]  (nearest 3x upsample fused), float4.
// -------------------------------------------------------------------------
__global__ void k_mul(const float* __restrict__ x, float* __restrict__ out) {
    int gid = blockIdx.x*256 + threadIdx.x;   // total = 16*64*192*48 float4 exactly
    int jq    = gid % 48;
    int rowid = gid / 48;
    int i = rowid % HH;
    int p = rowid / HH;
    float4 xv = ((const float4*)x)[gid];
    const float* grow = g_gate + (size_t)p*(HT*HT) + (i/3)*HT;
    int j0 = jq*4;
    float4 o;
    o.x = xv.x * grow[(j0+0)/3];
    o.y = xv.y * grow[(j0+1)/3];
    o.z = xv.z * grow[(j0+2)/3];
    o.w = xv.w * grow[(j0+3)/3];
    ((float4*)out)[gid] = o;
}

extern "C" void kernel_launch(void* const* d_in, const int* in_sizes, int n_in,
                              void* d_out, int out_size) {
    const float* x     = (const float*)d_in[0];
    const float* wh1   = (const float*)d_in[1];
    const float* wv1   = (const float*)d_in[2];
    const float* wh2   = (const float*)d_in[3];
    const float* wv2   = (const float*)d_in[4];
    const float* gamma = (const float*)d_in[5];
    const float* beta  = (const float*)d_in[6];
    const float* mean  = (const float*)d_in[7];
    const float* var   = (const float*)d_in[8];
    float* out = (float*)d_out;

    k_pool<<<dim3(16, BB*CC), dim3(64, 4)>>>(x);
    k_att<<<BB*CC, 256>>>(wh1, wv1, wh2, wv2, gamma, beta, mean, var);
    k_mul<<<(BB*CC*HH*(WW/4))/256, 256>>>(x, out);
}